// round 4
// baseline (speedup 1.0000x reference)
#include <cuda_runtime.h>
#include <cstdint>

// ResBlock_71021579207010 — fused binarized ResBlock (B=32, T=8192, C=F=128, K=2, dil=16).
//
// Reference algebra:
//   shortcut[b,t,f] = sum_c sign(x[b,t,c]) * sign(w_sc[0,c,f])          (exact binary dot)
//   conv2 input = ste_sign(relu(...)) == +1 everywhere (zero left-pad at t<16)  =>
//     conv2 out: t >= 16 : S0[f]+S1[f],  t < 16 : S1[f],  Sk[f] = sum_c sign(w2[k,c,f])
//   out = relu( relu(bn2(const)) + shortcut )
//   conv1 / bn1 / w1 / beta1 / mean1 / var1 are DEAD (reach output only through a constant sign).
//
// Main kernel: read x (128 MiB) -> ballot-pack signs -> xor/popc vs packed w_sc -> add
// per-channel const -> relu -> write out (128 MiB). Pure HBM-bound; floor ~43 us @6.3TB/s.

#define T_LEN   8192
#define C_DIM   128
#define F_DIM   128
#define B_DIM   32
#define ROWS_TOTAL (B_DIM * T_LEN)      // 262144

__device__ uint4 g_wsc[F_DIM];   // packed sign bits of w_sc: word k bit l <-> channel c = 4*l + k
__device__ float g_clo[F_DIM];   // relu(bn2(S1))        for t <  16
__device__ float g_chi[F_DIM];   // relu(bn2(S0 + S1))   for t >= 16

__global__ void precompute_kernel(const float* __restrict__ w2,    // [2,128,128]
                                  const float* __restrict__ w_sc,  // [1,128,128]
                                  const float* __restrict__ beta2,
                                  const float* __restrict__ mean2,
                                  const float* __restrict__ var2) {
    int f = threadIdx.x;
    if (f >= F_DIM) return;

    // Pack sign bits of w_sc[:, f] with the SAME permutation the main kernel's
    // ballots produce: word k, bit l  <->  channel c = 4*l + k.
    unsigned w[4] = {0u, 0u, 0u, 0u};
    #pragma unroll 4
    for (int l = 0; l < 32; ++l) {
        #pragma unroll
        for (int k = 0; k < 4; ++k) {
            int c = 4 * l + k;
            if (w_sc[c * F_DIM + f] < 0.0f) w[k] |= (1u << l);
        }
    }
    g_wsc[f] = make_uint4(w[0], w[1], w[2], w[3]);

    // Column sums of sign(w2[k,:,f])
    int n0 = 0, n1 = 0;
    for (int c = 0; c < C_DIM; ++c) {
        if (w2[(0 * C_DIM + c) * F_DIM + f] < 0.0f) n0++;
        if (w2[(1 * C_DIM + c) * F_DIM + f] < 0.0f) n1++;
    }
    float S0 = (float)(C_DIM - 2 * n0);
    float S1 = (float)(C_DIM - 2 * n1);

    float inv = rsqrtf(var2[f] + 1e-3f);
    float lo  = (S1      - mean2[f]) * inv + beta2[f];
    float hi  = (S0 + S1 - mean2[f]) * inv + beta2[f];
    g_clo[f] = fmaxf(lo, 0.0f);
    g_chi[f] = fmaxf(hi, 0.0f);
}

#define BLOCK_THREADS 256
#define WARPS_PER_BLOCK (BLOCK_THREADS / 32)              // 8
#define ROWS_PER_WARP 16
#define ROWS_PER_BLOCK (WARPS_PER_BLOCK * ROWS_PER_WARP)  // 128
#define GRID_BLOCKS (ROWS_TOTAL / ROWS_PER_BLOCK)         // 2048

__global__ __launch_bounds__(BLOCK_THREADS)
void resblock_main_kernel(const float* __restrict__ x, float* __restrict__ out) {
    __shared__ uint4 s_wsc[F_DIM];
    __shared__ float s_clo[F_DIM];
    __shared__ float s_chi[F_DIM];

    int tid = threadIdx.x;
    if (tid < F_DIM) {
        s_wsc[tid] = g_wsc[tid];
        s_clo[tid] = g_clo[tid];
        s_chi[tid] = g_chi[tid];
    }
    __syncthreads();

    const int lane = tid & 31;
    const int warp = tid >> 5;
    const int base = blockIdx.x * ROWS_PER_BLOCK;

    #pragma unroll 2
    for (int i = 0; i < ROWS_PER_WARP; ++i) {
        // Consecutive warps take consecutive rows each iteration -> the block walks
        // a contiguous 4 KiB chunk per iteration (coalesced, DRAM-friendly).
        const int r = base + i * WARPS_PER_BLOCK + warp;     // row = b*T + t
        const float4 v = *(const float4*)(x + (size_t)r * C_DIM + 4 * lane);

        // Packed sign bits of the x-row; ballot broadcasts the word to all lanes.
        // Word k bit l = sign(x[c = 4*l + k]) — matches the w_sc packing above.
        unsigned a0 = __ballot_sync(0xffffffffu, v.x < 0.0f);
        unsigned a1 = __ballot_sync(0xffffffffu, v.y < 0.0f);
        unsigned a2 = __ballot_sync(0xffffffffu, v.z < 0.0f);
        unsigned a3 = __ballot_sync(0xffffffffu, v.w < 0.0f);

        const int  t  = r & (T_LEN - 1);
        const bool hi = (t >= 16);

        float4 o;
        float* op = &o.x;
        #pragma unroll
        for (int j = 0; j < 4; ++j) {
            const int f = 4 * lane + j;
            const uint4 wb = s_wsc[f];
            int neq = __popc(a0 ^ wb.x) + __popc(a1 ^ wb.y)
                    + __popc(a2 ^ wb.z) + __popc(a3 ^ wb.w);
            float dot = (float)(C_DIM - 2 * neq);            // exact binary dot
            float cst = hi ? s_chi[f] : s_clo[f];
            op[j] = fmaxf(dot + cst, 0.0f);
        }
        *(float4*)(out + (size_t)r * F_DIM + 4 * lane) = o;
    }
}

extern "C" void kernel_launch(void* const* d_in, const int* in_sizes, int n_in,
                              void* d_out, int out_size) {
    // metadata order: x, w1, w2, w_sc, beta1, mean1, var1, beta2, mean2, var2
    const float* x     = (const float*)d_in[0];
    const float* w2    = (const float*)d_in[2];
    const float* w_sc  = (const float*)d_in[3];
    const float* beta2 = (const float*)d_in[7];
    const float* mean2 = (const float*)d_in[8];
    const float* var2  = (const float*)d_in[9];
    float* out = (float*)d_out;

    precompute_kernel<<<1, 128>>>(w2, w_sc, beta2, mean2, var2);
    resblock_main_kernel<<<GRID_BLOCKS, BLOCK_THREADS>>>(x, out);
}

// round 5
// speedup vs baseline: 1.5581x; 1.5581x over previous
#include <cuda_runtime.h>
#include <cstdint>

// ResBlock_71021579207010 — fused binarized ResBlock (B=32, T=8192, C=F=128, K=2, dil=16).
//
// Algebra (verified R4, rel_err 6.4e-8):
//   shortcut[b,t,f] = sum_c sign(x[b,t,c]) * sign(w_sc[0,c,f])           (exact binary dot)
//   conv2 input = ste_sign(relu(...)) == +1  =>  conv2 out is constant per (t<16 | t>=16)
//   conv1/bn1/w1/beta1/mean1/var1 are dead.
//   out = relu( shortcut + relu(bn2(const)) )
//
// R5 changes vs R4:
//   * weight words + constants hoisted to REGISTERS (f = 4*lane+j is loop-invariant)
//     -> inner loop has ZERO shared-memory accesses (R4 had a 16-way-conflicted LDS.128
//        stream that pinned l1tex at 84% and capped DRAM at 44%).
//   * constants pre-biased by +128 so the epilogue is one FFMA per output.
//   * precompute kernel parallelized warp-per-f (ballot packing + warp reductions).

#define T_LEN   8192
#define C_DIM   128
#define F_DIM   128
#define B_DIM   32
#define ROWS_TOTAL (B_DIM * T_LEN)      // 262144

__device__ uint4 g_wsc[F_DIM];    // packed sign(w_sc): word k bit l <-> channel c = 4*l + k
__device__ float g_clo[F_DIM];    // 128 + relu(bn2(S1))       for t <  16
__device__ float g_chi[F_DIM];    // 128 + relu(bn2(S0+S1))    for t >= 16

// One warp per output channel f. The w_sc bit packing is done with the SAME
// ballot construction the main kernel uses on x, so conventions match by design.
__global__ void precompute_kernel(const float* __restrict__ w2,    // [2,128,128]
                                  const float* __restrict__ w_sc,  // [1,128,128]
                                  const float* __restrict__ beta2,
                                  const float* __restrict__ mean2,
                                  const float* __restrict__ var2) {
    const int f = blockIdx.x;          // 0..127
    const int l = threadIdx.x;         // lane 0..31

    // word k, bit l  <->  channel c = 4*l + k
    unsigned w0 = __ballot_sync(0xffffffffu, w_sc[(4 * l + 0) * F_DIM + f] < 0.0f);
    unsigned w1 = __ballot_sync(0xffffffffu, w_sc[(4 * l + 1) * F_DIM + f] < 0.0f);
    unsigned w2b = __ballot_sync(0xffffffffu, w_sc[(4 * l + 2) * F_DIM + f] < 0.0f);
    unsigned w3 = __ballot_sync(0xffffffffu, w_sc[(4 * l + 3) * F_DIM + f] < 0.0f);

    // Column sums of sign(w2[k,:,f]): count negatives via ballot popc, 4 chans/lane.
    int n0 = 0, n1 = 0;
    #pragma unroll
    for (int j = 0; j < 4; ++j) {
        int c = 4 * l + j;
        n0 += __popc(__ballot_sync(0xffffffffu, w2[(0 * C_DIM + c) * F_DIM + f] < 0.0f)) & (l == 0 ? ~0 : 0);
        n1 += __popc(__ballot_sync(0xffffffffu, w2[(1 * C_DIM + c) * F_DIM + f] < 0.0f)) & (l == 0 ? ~0 : 0);
    }

    if (l == 0) {
        g_wsc[f] = make_uint4(w0, w1, w2b, w3);
        float S0 = (float)(C_DIM - 2 * n0);
        float S1 = (float)(C_DIM - 2 * n1);
        float inv = rsqrtf(var2[f] + 1e-3f);
        float lo  = (S1      - mean2[f]) * inv + beta2[f];
        float hi  = (S0 + S1 - mean2[f]) * inv + beta2[f];
        // pre-bias by +C_DIM: out = relu( (C_DIM - 2*neq) + relu(bn) ) = relu(fma(neq,-2,cst))
        g_clo[f] = fmaxf(lo, 0.0f) + (float)C_DIM;
        g_chi[f] = fmaxf(hi, 0.0f) + (float)C_DIM;
    }
}

#define BLOCK_THREADS 256
#define WARPS_PER_BLOCK (BLOCK_THREADS / 32)              // 8
#define ROWS_PER_WARP 16
#define ROWS_PER_BLOCK (WARPS_PER_BLOCK * ROWS_PER_WARP)  // 128
#define GRID_BLOCKS (ROWS_TOTAL / ROWS_PER_BLOCK)         // 2048

__global__ __launch_bounds__(BLOCK_THREADS)
void resblock_main_kernel(const float* __restrict__ x, float* __restrict__ out) {
    const int lane = threadIdx.x & 31;
    const int warp = threadIdx.x >> 5;
    const int base = blockIdx.x * ROWS_PER_BLOCK;

    // Hoist per-thread weights/constants into registers (loop-invariant: f = 4*lane+j).
    const int fb = 4 * lane;
    const uint4 wb0 = g_wsc[fb + 0];
    const uint4 wb1 = g_wsc[fb + 1];
    const uint4 wb2 = g_wsc[fb + 2];
    const uint4 wb3 = g_wsc[fb + 3];
    const float4 chi = make_float4(g_chi[fb], g_chi[fb + 1], g_chi[fb + 2], g_chi[fb + 3]);
    const float4 clo = make_float4(g_clo[fb], g_clo[fb + 1], g_clo[fb + 2], g_clo[fb + 3]);

    #pragma unroll 4
    for (int i = 0; i < ROWS_PER_WARP; ++i) {
        // Consecutive warps take consecutive rows each iteration -> the block walks
        // contiguous 4 KiB chunks (fully coalesced 128B segments).
        const int r = base + i * WARPS_PER_BLOCK + warp;     // row = b*T + t
        const float4 v = *(const float4*)(x + (size_t)r * C_DIM + 4 * lane);

        // Packed sign bits of the x-row; ballot broadcasts each word to all lanes.
        // Word k bit l = sign(x[c = 4*l + k]) — matches the w_sc packing.
        const unsigned a0 = __ballot_sync(0xffffffffu, v.x < 0.0f);
        const unsigned a1 = __ballot_sync(0xffffffffu, v.y < 0.0f);
        const unsigned a2 = __ballot_sync(0xffffffffu, v.z < 0.0f);
        const unsigned a3 = __ballot_sync(0xffffffffu, v.w < 0.0f);

        const bool hi = ((r & (T_LEN - 1)) >= 16);

        const int n0 = __popc(a0 ^ wb0.x) + __popc(a1 ^ wb0.y) + __popc(a2 ^ wb0.z) + __popc(a3 ^ wb0.w);
        const int n1 = __popc(a0 ^ wb1.x) + __popc(a1 ^ wb1.y) + __popc(a2 ^ wb1.z) + __popc(a3 ^ wb1.w);
        const int n2 = __popc(a0 ^ wb2.x) + __popc(a1 ^ wb2.y) + __popc(a2 ^ wb2.z) + __popc(a3 ^ wb2.w);
        const int n3 = __popc(a0 ^ wb3.x) + __popc(a1 ^ wb3.y) + __popc(a2 ^ wb3.z) + __popc(a3 ^ wb3.w);

        float4 o;
        o.x = fmaxf(fmaf((float)n0, -2.0f, hi ? chi.x : clo.x), 0.0f);
        o.y = fmaxf(fmaf((float)n1, -2.0f, hi ? chi.y : clo.y), 0.0f);
        o.z = fmaxf(fmaf((float)n2, -2.0f, hi ? chi.z : clo.z), 0.0f);
        o.w = fmaxf(fmaf((float)n3, -2.0f, hi ? chi.w : clo.w), 0.0f);

        *(float4*)(out + (size_t)r * F_DIM + 4 * lane) = o;
    }
}

extern "C" void kernel_launch(void* const* d_in, const int* in_sizes, int n_in,
                              void* d_out, int out_size) {
    // metadata order: x, w1, w2, w_sc, beta1, mean1, var1, beta2, mean2, var2
    const float* x     = (const float*)d_in[0];
    const float* w2    = (const float*)d_in[2];
    const float* w_sc  = (const float*)d_in[3];
    const float* beta2 = (const float*)d_in[7];
    const float* mean2 = (const float*)d_in[8];
    const float* var2  = (const float*)d_in[9];
    float* out = (float*)d_out;

    precompute_kernel<<<F_DIM, 32>>>(w2, w_sc, beta2, mean2, var2);
    resblock_main_kernel<<<GRID_BLOCKS, BLOCK_THREADS>>>(x, out);
}